// round 8
// baseline (speedup 1.0000x reference)
#include <cuda_runtime.h>
#include <cuda_fp16.h>
#include <math.h>
#include <stdint.h>

#define NROWS 16384
#define FIN   512
#define FHID  256

// ---------------- scratch (__device__ globals; no allocation) ----------------
__device__ __half g_xh [(size_t)NROWS * FIN];     // 16 MiB  x in fp16
__device__ __half g_WTh[(size_t)FHID * FIN];      // 256 KiB Wᵀ fp16
__device__ __half g_sT [(size_t)FHID * NROWS];    // 8 MiB   supportᵀ fp16
__device__ float  g_embed_fallback[(size_t)NROWS * FHID];

// ---------------- asm helpers (arch-neutral PTX, sm_80+) ----------------
__device__ __forceinline__ uint32_t smem_u32(const void* p) {
    uint32_t a;
    asm("{ .reg .u64 t; cvta.to.shared.u64 t, %1; cvt.u32.u64 %0, t; }" : "=r"(a) : "l"(p));
    return a;
}
#define CP_ASYNC16(dst, src) \
    asm volatile("cp.async.cg.shared.global [%0], [%1], 16;" :: "r"(dst), "l"(src))
#define CP_COMMIT() asm volatile("cp.async.commit_group;" ::: "memory")
#define CP_WAIT1()  asm volatile("cp.async.wait_group 1;" ::: "memory")
#define CP_WAIT0()  asm volatile("cp.async.wait_group 0;" ::: "memory")
#define LDSM4(r, a) \
    asm volatile("ldmatrix.sync.aligned.m8n8.x4.shared.b16 {%0,%1,%2,%3}, [%4];" \
        : "=r"((r)[0]), "=r"((r)[1]), "=r"((r)[2]), "=r"((r)[3]) : "r"(a))
#define MMA16816(c, a, b) \
    asm volatile("mma.sync.aligned.m16n8k16.row.col.f32.f16.f16.f32 " \
        "{%0,%1,%2,%3}, {%4,%5,%6,%7}, {%8,%9}, {%0,%1,%2,%3};" \
        : "+f"((c)[0]), "+f"((c)[1]), "+f"((c)[2]), "+f"((c)[3]) \
        : "r"((a)[0]), "r"((a)[1]), "r"((a)[2]), "r"((a)[3]), "r"((b)[0]), "r"((b)[1]))

// ====== prep 1: W [512,256] fp32 -> WT [256,512] fp16 ======
__global__ __launch_bounds__(256)
void wt_half(const float* __restrict__ W, __half* __restrict__ Th)
{
    __shared__ float ts[32][33];
    const int f0 = blockIdx.x * 32, h0 = blockIdx.y * 32;
    const int tx = threadIdx.x & 31, ty = threadIdx.x >> 5;  // 32 x 8
    #pragma unroll
    for (int k = 0; k < 4; k++)
        ts[ty + 8 * k][tx] = W[(size_t)(f0 + ty + 8 * k) * FHID + h0 + tx];
    __syncthreads();
    #pragma unroll
    for (int k = 0; k < 4; k++) {
        int h = h0 + ty + 8 * k, f = f0 + tx;
        Th[(size_t)h * FIN + f] = __float2half_rn(ts[tx][ty + 8 * k]);
    }
}

// ====== prep 2: x fp32 -> fp16 elementwise ======
__global__ __launch_bounds__(256)
void x_half(const float* __restrict__ X, __half* __restrict__ Xh)
{
    size_t i = ((size_t)blockIdx.x * 256 + threadIdx.x) * 4;
    float4 v = *reinterpret_cast<const float4*>(X + i);
    __half2 h0 = __float22half2_rn(make_float2(v.x, v.y));
    __half2 h1 = __float22half2_rn(make_float2(v.z, v.w));
    *reinterpret_cast<uint2*>(Xh + i) =
        make_uint2(*reinterpret_cast<uint32_t*>(&h0), *reinterpret_cast<uint32_t*>(&h1));
}

// ====== GEMM1 (HMMA): sT[h][n] = WT @ x_fp16, output fp16 ======
// grid (FHID/64, NROWS/256); 256 thr = 8 warps (2Mx4N), warptile 32x64, BK=64.
#define G1_SBST 32768                    // B stage: 256 rows * 128B
#define G1_SA   (2 * G1_SBST)            // A stages after B's two
#define G1_SAST 8192                     // A stage: 64 rows * 128B
#define G1_SMEM (G1_SA + 2 * G1_SAST)    // 81920
#define NCH1 (FIN / 64)                  // 8 chunks

__global__ __launch_bounds__(256, 2)
void gemm1_hmma(const __half* __restrict__ WTh,
                const __half* __restrict__ Xh, __half* __restrict__ sT)
{
    extern __shared__ char sm[];
    const uint32_t sb = smem_u32(sm);
    const int tid  = threadIdx.x;
    const int lane = tid & 31, wid = tid >> 5;
    const int wm = wid >> 2, wn = wid & 3;
    const int mblk = blockIdx.x * 64, nblk = blockIdx.y * 256;

    float acc[2][8][4];
    #pragma unroll
    for (int i = 0; i < 2; i++)
        #pragma unroll
        for (int j = 0; j < 8; j++)
            #pragma unroll
            for (int q = 0; q < 4; q++) acc[i][j][q] = 0.0f;

    auto issue = [&](int c, int s) {
        const size_t k0 = (size_t)c * 64;
        // B (x): 256 rows x 64 halves (8 x 16B/thr)
        #pragma unroll
        for (int i = 0; i < 8; i++) {
            int o = tid + i * 256;
            int row = o >> 3, kc = o & 7;
            uint32_t dst = sb + (uint32_t)s * G1_SBST + (uint32_t)row * 128
                         + (uint32_t)((kc ^ (row & 7)) << 4);
            CP_ASYNC16(dst, Xh + (size_t)(nblk + row) * FIN + k0 + kc * 8);
        }
        // A (WT): 64 rows x 64 halves (2 x 16B/thr)
        #pragma unroll
        for (int i = 0; i < 2; i++) {
            int o = tid + i * 256;
            int row = o >> 3, kc = o & 7;
            uint32_t so = (uint32_t)row * 128 + (uint32_t)((kc ^ (row & 7)) << 4);
            CP_ASYNC16(sb + G1_SA + (uint32_t)s * G1_SAST + so,
                       WTh + (size_t)(mblk + row) * FIN + k0 + kc * 8);
        }
    };
    auto compute = [&](int s) {
        const uint32_t baseB = sb + (uint32_t)s * G1_SBST;
        const uint32_t baseA = sb + G1_SA + (uint32_t)s * G1_SAST;
        #pragma unroll
        for (int kk = 0; kk < 4; kk++) {
            uint32_t ah[2][4];
            const int arow = lane & 15;
            const int uA = kk * 2 + (lane >> 4);
            #pragma unroll
            for (int mi = 0; mi < 2; mi++) {
                int r = wm * 32 + mi * 16 + arow;
                LDSM4(ah[mi], baseA + (uint32_t)r * 128 + (uint32_t)((uA ^ (r & 7)) << 4));
            }
            #pragma unroll
            for (int g = 0; g < 4; g++) {
                const int nrow = wn * 64 + g * 16 + (lane & 7) + ((lane >> 4) << 3);
                const int uB = kk * 2 + ((lane >> 3) & 1);
                uint32_t bh[4];
                LDSM4(bh, baseB + (uint32_t)nrow * 128 + (uint32_t)((uB ^ (nrow & 7)) << 4));
                #pragma unroll
                for (int mi = 0; mi < 2; mi++)
                    #pragma unroll
                    for (int q = 0; q < 2; q++)
                        MMA16816(acc[mi][g * 2 + q], ah[mi], &bh[2 * q]);
            }
        }
    };

    issue(0, 0); CP_COMMIT();
    issue(1, 1); CP_COMMIT();
    for (int c = 0; c < NCH1; ++c) {
        if (c + 1 < NCH1) CP_WAIT1(); else CP_WAIT0();
        __syncthreads();
        compute(c & 1);
        __syncthreads();
        if (c + 2 < NCH1) { issue(c + 2, c & 1); CP_COMMIT(); }
    }

    // epilogue: fp16 store to sT[h][n]
    #pragma unroll
    for (int ni = 0; ni < 8; ni++) {
        const int col = nblk + wn * 64 + ni * 8 + (lane & 3) * 2;
        #pragma unroll
        for (int mi = 0; mi < 2; mi++) {
            const int h0 = mblk + wm * 32 + mi * 16 + (lane >> 2);
            const float* c = acc[mi][ni];
            __half2 v0 = __float22half2_rn(make_float2(c[0], c[1]));
            __half2 v1 = __float22half2_rn(make_float2(c[2], c[3]));
            *reinterpret_cast<__half2*>(sT + (size_t)h0 * NROWS + col) = v0;
            *reinterpret_cast<__half2*>(sT + (size_t)(h0 + 8) * NROWS + col) = v1;
        }
    }
}

// ===== GEMM2 + bias + log_softmax fused (floored HMMA mainloop) =====
#define BM2 64
#define BK2 64
#define SBST 32768
#define SA_OFF (3 * SBST)
#define SAST 8192
#define G2_SMEM (SA_OFF + 2 * SAST)
#define NCH2  (NROWS / BK2)

__global__ __launch_bounds__(256, 2)
void gemm2_fused(const float* __restrict__ adj,
                 const __half* __restrict__ Bh,
                 const float* __restrict__ bias,
                 float* __restrict__ embed,
                 float* __restrict__ logp)
{
    extern __shared__ char sm[];
    const uint32_t sb = smem_u32(sm);
    const int tid  = threadIdx.x;
    const int lane = tid & 31, wid = tid >> 5;
    const int wm = wid >> 2, wn = wid & 3;
    const int mblk = blockIdx.x * BM2;

    float acc[2][8][4];
    #pragma unroll
    for (int i = 0; i < 2; i++)
        #pragma unroll
        for (int j = 0; j < 8; j++)
            #pragma unroll
            for (int q = 0; q < 4; q++) acc[i][j][q] = 0.0f;

    auto issueB = [&](int c, int s) {
        const size_t k0 = (size_t)c * BK2;
        #pragma unroll
        for (int i = 0; i < 8; i++) {
            int o = tid + i * 256;
            int row = o >> 3, kc = o & 7;
            uint32_t dst = sb + (uint32_t)s * SBST + (uint32_t)row * 128
                         + (uint32_t)((kc ^ (row & 7)) << 4);
            CP_ASYNC16(dst, Bh + (size_t)row * NROWS + k0 + kc * 8);
        }
    };
    const int arow_ = tid >> 2, aq = tid & 3;
    auto ldgA = [&](int c, float4 av[4]) {
        const float* p = adj + (size_t)(mblk + arow_) * NROWS + (size_t)c * BK2 + aq * 16;
        av[0] = reinterpret_cast<const float4*>(p)[0];
        av[1] = reinterpret_cast<const float4*>(p)[1];
        av[2] = reinterpret_cast<const float4*>(p)[2];
        av[3] = reinterpret_cast<const float4*>(p)[3];
    };
    auto storeA = [&](const float4 av[4], int d) {
        uint32_t w[8];
        #pragma unroll
        for (int i = 0; i < 4; i++) {
            __half2 h0 = __float22half2_rn(make_float2(av[i].x, av[i].y));
            __half2 h1 = __float22half2_rn(make_float2(av[i].z, av[i].w));
            w[2 * i]     = *reinterpret_cast<uint32_t*>(&h0);
            w[2 * i + 1] = *reinterpret_cast<uint32_t*>(&h1);
        }
        uint32_t base = sb + SA_OFF + (uint32_t)d * SAST + (uint32_t)arow_ * 128;
        uint32_t u0 = (uint32_t)((aq * 2) ^ (arow_ & 7)) << 4;
        uint32_t u1 = (uint32_t)((aq * 2 + 1) ^ (arow_ & 7)) << 4;
        asm volatile("st.shared.v4.b32 [%0], {%1,%2,%3,%4};" ::
            "r"(base + u0), "r"(w[0]), "r"(w[1]), "r"(w[2]), "r"(w[3]));
        asm volatile("st.shared.v4.b32 [%0], {%1,%2,%3,%4};" ::
            "r"(base + u1), "r"(w[4]), "r"(w[5]), "r"(w[6]), "r"(w[7]));
    };
    auto compute = [&](int bs, int ad) {
        const uint32_t baseB = sb + (uint32_t)bs * SBST;
        const uint32_t baseA = sb + SA_OFF + (uint32_t)ad * SAST;
        #pragma unroll
        for (int kk = 0; kk < 4; kk++) {
            uint32_t ah[2][4];
            const int arow = lane & 15;
            const int uA = kk * 2 + (lane >> 4);
            #pragma unroll
            for (int mi = 0; mi < 2; mi++) {
                int r = wm * 32 + mi * 16 + arow;
                LDSM4(ah[mi], baseA + (uint32_t)r * 128 + (uint32_t)((uA ^ (r & 7)) << 4));
            }
            #pragma unroll
            for (int g = 0; g < 4; g++) {
                const int nrow = wn * 64 + g * 16 + (lane & 7) + ((lane >> 4) << 3);
                const int uB = kk * 2 + ((lane >> 3) & 1);
                uint32_t bh[4];
                LDSM4(bh, baseB + (uint32_t)nrow * 128 + (uint32_t)((uB ^ (nrow & 7)) << 4));
                #pragma unroll
                for (int mi = 0; mi < 2; mi++)
                    #pragma unroll
                    for (int q = 0; q < 2; q++)
                        MMA16816(acc[mi][g * 2 + q], ah[mi], &bh[2 * q]);
            }
        }
    };

    issueB(0, 0); CP_COMMIT();
    issueB(1, 1); CP_COMMIT();
    float4 av[4];
    ldgA(0, av); storeA(av, 0);
    ldgA(1, av);

    for (int c = 0; c < NCH2; ++c) {
        __syncthreads();                 // protects A-buf + B-stage reuse
        if (c + 1 < NCH2) storeA(av, (c + 1) & 1);   // STS overlaps async wait
        if (c < NCH2 - 1) CP_WAIT1(); else CP_WAIT0();
        compute(c % 3, c & 1);
        if (c + 2 < NCH2) { issueB(c + 2, (c + 2) % 3); CP_COMMIT(); }
        if (c + 2 < NCH2) ldgA(c + 2, av);
    }
    __syncthreads();

    #pragma unroll
    for (int ni = 0; ni < 8; ni++) {
        const float2 bv = __ldg(reinterpret_cast<const float2*>(
            bias + wn * 64 + ni * 8 + (lane & 3) * 2));
        #pragma unroll
        for (int mi = 0; mi < 2; mi++) {
            acc[mi][ni][0] += bv.x; acc[mi][ni][1] += bv.y;
            acc[mi][ni][2] += bv.x; acc[mi][ni][3] += bv.y;
        }
    }
    float* part  = reinterpret_cast<float*>(sm);
    float* part2 = reinterpret_cast<float*>(sm + 1024);
    float mx[2][2];
    #pragma unroll
    for (int mi = 0; mi < 2; mi++)
        #pragma unroll
        for (int rh = 0; rh < 2; rh++) {
            float m = -INFINITY;
            #pragma unroll
            for (int ni = 0; ni < 8; ni++)
                m = fmaxf(m, fmaxf(acc[mi][ni][rh * 2], acc[mi][ni][rh * 2 + 1]));
            m = fmaxf(m, __shfl_xor_sync(0xffffffffu, m, 1));
            m = fmaxf(m, __shfl_xor_sync(0xffffffffu, m, 2));
            mx[mi][rh] = m;
        }
    if ((lane & 3) == 0) {
        #pragma unroll
        for (int mi = 0; mi < 2; mi++)
            #pragma unroll
            for (int rh = 0; rh < 2; rh++)
                part[(wm * 32 + mi * 16 + (lane >> 2) + rh * 8) * 4 + wn] = mx[mi][rh];
    }
    __syncthreads();
    float rmax[2][2];
    #pragma unroll
    for (int mi = 0; mi < 2; mi++)
        #pragma unroll
        for (int rh = 0; rh < 2; rh++) {
            int r = wm * 32 + mi * 16 + (lane >> 2) + rh * 8;
            rmax[mi][rh] = fmaxf(fmaxf(part[r * 4], part[r * 4 + 1]),
                                 fmaxf(part[r * 4 + 2], part[r * 4 + 3]));
        }
    float sme[2][2];
    #pragma unroll
    for (int mi = 0; mi < 2; mi++)
        #pragma unroll
        for (int rh = 0; rh < 2; rh++) {
            float s = 0.0f;
            #pragma unroll
            for (int ni = 0; ni < 8; ni++)
                s += __expf(acc[mi][ni][rh * 2] - rmax[mi][rh])
                   + __expf(acc[mi][ni][rh * 2 + 1] - rmax[mi][rh]);
            s += __shfl_xor_sync(0xffffffffu, s, 1);
            s += __shfl_xor_sync(0xffffffffu, s, 2);
            sme[mi][rh] = s;
        }
    if ((lane & 3) == 0) {
        #pragma unroll
        for (int mi = 0; mi < 2; mi++)
            #pragma unroll
            for (int rh = 0; rh < 2; rh++)
                part2[(wm * 32 + mi * 16 + (lane >> 2) + rh * 8) * 4 + wn] = sme[mi][rh];
    }
    __syncthreads();
    float lse[2][2];
    #pragma unroll
    for (int mi = 0; mi < 2; mi++)
        #pragma unroll
        for (int rh = 0; rh < 2; rh++) {
            int r = wm * 32 + mi * 16 + (lane >> 2) + rh * 8;
            lse[mi][rh] = rmax[mi][rh] + __logf(part2[r * 4] + part2[r * 4 + 1]
                                              + part2[r * 4 + 2] + part2[r * 4 + 3]);
        }
    #pragma unroll
    for (int ni = 0; ni < 8; ni++) {
        const int col = wn * 64 + ni * 8 + (lane & 3) * 2;
        #pragma unroll
        for (int mi = 0; mi < 2; mi++) {
            const int r0 = mblk + wm * 32 + mi * 16 + (lane >> 2);
            const float* c = acc[mi][ni];
            *reinterpret_cast<float2*>(embed + (size_t)r0 * FHID + col) =
                make_float2(c[0], c[1]);
            *reinterpret_cast<float2*>(embed + (size_t)(r0 + 8) * FHID + col) =
                make_float2(c[2], c[3]);
            *reinterpret_cast<float2*>(logp + (size_t)r0 * FHID + col) =
                make_float2(c[0] - lse[mi][0], c[1] - lse[mi][0]);
            *reinterpret_cast<float2*>(logp + (size_t)(r0 + 8) * FHID + col) =
                make_float2(c[2] - lse[mi][1], c[3] - lse[mi][1]);
        }
    }
}

// ================= launch =================
extern "C" void kernel_launch(void* const* d_in, const int* in_sizes, int n_in,
                              void* d_out, int out_size)
{
    const float* x   = (const float*)d_in[0];
    const float* adj = (const float*)d_in[1];
    const float* W   = (const float*)d_in[2];
    const float* b   = (const float*)d_in[3];
    float* out = (float*)d_out;

    float* embed;
    __half *xh, *WTh, *sT;
    cudaGetSymbolAddress((void**)&xh,  g_xh);
    cudaGetSymbolAddress((void**)&WTh, g_WTh);
    cudaGetSymbolAddress((void**)&sT,  g_sT);

    float* logp = out;
    if (out_size >= 2 * NROWS * FHID) embed = out + (size_t)NROWS * FHID;
    else cudaGetSymbolAddress((void**)&embed, g_embed_fallback);

    cudaFuncSetAttribute(gemm1_hmma, cudaFuncAttributeMaxDynamicSharedMemorySize, G1_SMEM);
    cudaFuncSetAttribute(gemm2_fused, cudaFuncAttributeMaxDynamicSharedMemorySize, G2_SMEM);

    // prep: WT fp16, x fp16
    wt_half<<<dim3(FIN / 32, FHID / 32), 256>>>(W, WTh);
    x_half<<<(NROWS * FIN) / 1024, 256>>>(x, xh);
    // GEMM1 (HMMA, 1-term): sT = WT @ xT, fp16 out, already transposed
    gemm1_hmma<<<dim3(FHID / 64, NROWS / 256), 256, G1_SMEM>>>(WTh, xh, sT);
    // GEMM2 + bias + log_softmax fused
    gemm2_fused<<<NROWS / BM2, 256, G2_SMEM>>>(adj, sT, b, embed, logp);
}

// round 9
// speedup vs baseline: 1.0333x; 1.0333x over previous
#include <cuda_runtime.h>
#include <cuda_fp16.h>
#include <math.h>
#include <stdint.h>

#define NROWS 16384
#define FIN   512
#define FHID  256

// ---------------- scratch (__device__ globals; no allocation) ----------------
__device__ __half g_xh [(size_t)NROWS * FIN];     // 16 MiB  x in fp16
__device__ __half g_WTh[(size_t)FHID * FIN];      // 256 KiB Wᵀ fp16
__device__ __half g_sT [(size_t)FHID * NROWS];    // 8 MiB   supportᵀ fp16
__device__ float  g_embed_fallback[(size_t)NROWS * FHID];

// ---------------- asm helpers (arch-neutral PTX, sm_80+) ----------------
__device__ __forceinline__ uint32_t smem_u32(const void* p) {
    uint32_t a;
    asm("{ .reg .u64 t; cvta.to.shared.u64 t, %1; cvt.u32.u64 %0, t; }" : "=r"(a) : "l"(p));
    return a;
}
#define CP_ASYNC16(dst, src) \
    asm volatile("cp.async.cg.shared.global [%0], [%1], 16;" :: "r"(dst), "l"(src))
#define CP_COMMIT() asm volatile("cp.async.commit_group;" ::: "memory")
#define CP_WAIT1()  asm volatile("cp.async.wait_group 1;" ::: "memory")
#define CP_WAIT0()  asm volatile("cp.async.wait_group 0;" ::: "memory")
#define LDSM4(r, a) \
    asm volatile("ldmatrix.sync.aligned.m8n8.x4.shared.b16 {%0,%1,%2,%3}, [%4];" \
        : "=r"((r)[0]), "=r"((r)[1]), "=r"((r)[2]), "=r"((r)[3]) : "r"(a))
#define MMA16816(c, a, b) \
    asm volatile("mma.sync.aligned.m16n8k16.row.col.f32.f16.f16.f32 " \
        "{%0,%1,%2,%3}, {%4,%5,%6,%7}, {%8,%9}, {%0,%1,%2,%3};" \
        : "+f"((c)[0]), "+f"((c)[1]), "+f"((c)[2]), "+f"((c)[3]) \
        : "r"((a)[0]), "r"((a)[1]), "r"((a)[2]), "r"((a)[3]), "r"((b)[0]), "r"((b)[1]))

// ====== prep 1: W [512,256] fp32 -> WT [256,512] fp16 ======
__global__ __launch_bounds__(256)
void wt_half(const float* __restrict__ W, __half* __restrict__ Th)
{
    __shared__ float ts[32][33];
    const int f0 = blockIdx.x * 32, h0 = blockIdx.y * 32;
    const int tx = threadIdx.x & 31, ty = threadIdx.x >> 5;  // 32 x 8
    #pragma unroll
    for (int k = 0; k < 4; k++)
        ts[ty + 8 * k][tx] = W[(size_t)(f0 + ty + 8 * k) * FHID + h0 + tx];
    __syncthreads();
    #pragma unroll
    for (int k = 0; k < 4; k++) {
        int h = h0 + ty + 8 * k, f = f0 + tx;
        Th[(size_t)h * FIN + f] = __float2half_rn(ts[tx][ty + 8 * k]);
    }
}

// ====== prep 2: x fp32 -> fp16 elementwise ======
__global__ __launch_bounds__(256)
void x_half(const float* __restrict__ X, __half* __restrict__ Xh)
{
    size_t i = ((size_t)blockIdx.x * 256 + threadIdx.x) * 4;
    float4 v = *reinterpret_cast<const float4*>(X + i);
    __half2 h0 = __float22half2_rn(make_float2(v.x, v.y));
    __half2 h1 = __float22half2_rn(make_float2(v.z, v.w));
    *reinterpret_cast<uint2*>(Xh + i) =
        make_uint2(*reinterpret_cast<uint32_t*>(&h0), *reinterpret_cast<uint32_t*>(&h1));
}

// ====== GEMM1 (HMMA): sT[h][n] = WT @ x_fp16, output fp16 ======
// grid (FHID/64, NROWS/256); 256 thr = 8 warps (2Mx4N), warptile 32x64, BK=64.
#define G1_SBST 32768                    // B stage: 256 rows * 128B
#define G1_SA   (2 * G1_SBST)            // A stages after B's two
#define G1_SAST 8192                     // A stage: 64 rows * 128B
#define G1_SMEM (G1_SA + 2 * G1_SAST)    // 81920
#define NCH1 (FIN / 64)                  // 8 chunks

__global__ __launch_bounds__(256, 2)
void gemm1_hmma(const __half* __restrict__ WTh,
                const __half* __restrict__ Xh, __half* __restrict__ sT)
{
    extern __shared__ char sm[];
    const uint32_t sb = smem_u32(sm);
    const int tid  = threadIdx.x;
    const int lane = tid & 31, wid = tid >> 5;
    const int wm = wid >> 2, wn = wid & 3;
    const int mblk = blockIdx.x * 64, nblk = blockIdx.y * 256;

    float acc[2][8][4];
    #pragma unroll
    for (int i = 0; i < 2; i++)
        #pragma unroll
        for (int j = 0; j < 8; j++)
            #pragma unroll
            for (int q = 0; q < 4; q++) acc[i][j][q] = 0.0f;

    auto issue = [&](int c, int s) {
        const size_t k0 = (size_t)c * 64;
        #pragma unroll
        for (int i = 0; i < 8; i++) {
            int o = tid + i * 256;
            int row = o >> 3, kc = o & 7;
            uint32_t dst = sb + (uint32_t)s * G1_SBST + (uint32_t)row * 128
                         + (uint32_t)((kc ^ (row & 7)) << 4);
            CP_ASYNC16(dst, Xh + (size_t)(nblk + row) * FIN + k0 + kc * 8);
        }
        #pragma unroll
        for (int i = 0; i < 2; i++) {
            int o = tid + i * 256;
            int row = o >> 3, kc = o & 7;
            uint32_t so = (uint32_t)row * 128 + (uint32_t)((kc ^ (row & 7)) << 4);
            CP_ASYNC16(sb + G1_SA + (uint32_t)s * G1_SAST + so,
                       WTh + (size_t)(mblk + row) * FIN + k0 + kc * 8);
        }
    };
    auto compute = [&](int s) {
        const uint32_t baseB = sb + (uint32_t)s * G1_SBST;
        const uint32_t baseA = sb + G1_SA + (uint32_t)s * G1_SAST;
        #pragma unroll
        for (int kk = 0; kk < 4; kk++) {
            uint32_t ah[2][4];
            const int arow = lane & 15;
            const int uA = kk * 2 + (lane >> 4);
            #pragma unroll
            for (int mi = 0; mi < 2; mi++) {
                int r = wm * 32 + mi * 16 + arow;
                LDSM4(ah[mi], baseA + (uint32_t)r * 128 + (uint32_t)((uA ^ (r & 7)) << 4));
            }
            #pragma unroll
            for (int g = 0; g < 4; g++) {
                const int nrow = wn * 64 + g * 16 + (lane & 7) + ((lane >> 4) << 3);
                const int uB = kk * 2 + ((lane >> 3) & 1);
                uint32_t bh[4];
                LDSM4(bh, baseB + (uint32_t)nrow * 128 + (uint32_t)((uB ^ (nrow & 7)) << 4));
                #pragma unroll
                for (int mi = 0; mi < 2; mi++)
                    #pragma unroll
                    for (int q = 0; q < 2; q++)
                        MMA16816(acc[mi][g * 2 + q], ah[mi], &bh[2 * q]);
            }
        }
    };

    issue(0, 0); CP_COMMIT();
    issue(1, 1); CP_COMMIT();
    for (int c = 0; c < NCH1; ++c) {
        if (c + 1 < NCH1) CP_WAIT1(); else CP_WAIT0();
        __syncthreads();
        compute(c & 1);
        __syncthreads();
        if (c + 2 < NCH1) { issue(c + 2, c & 1); CP_COMMIT(); }
    }

    #pragma unroll
    for (int ni = 0; ni < 8; ni++) {
        const int col = nblk + wn * 64 + ni * 8 + (lane & 3) * 2;
        #pragma unroll
        for (int mi = 0; mi < 2; mi++) {
            const int h0 = mblk + wm * 32 + mi * 16 + (lane >> 2);
            const float* c = acc[mi][ni];
            __half2 v0 = __float22half2_rn(make_float2(c[0], c[1]));
            __half2 v1 = __float22half2_rn(make_float2(c[2], c[3]));
            *reinterpret_cast<__half2*>(sT + (size_t)h0 * NROWS + col) = v0;
            *reinterpret_cast<__half2*>(sT + (size_t)(h0 + 8) * NROWS + col) = v1;
        }
    }
}

// ===== GEMM2 + bias + log_softmax fused (R7 loop order restored) =====
#define BM2 64
#define BK2 64
#define SBST 32768
#define SA_OFF (3 * SBST)
#define SAST 8192
#define G2_SMEM (SA_OFF + 2 * SAST)
#define NCH2  (NROWS / BK2)

__global__ __launch_bounds__(256, 2)
void gemm2_fused(const float* __restrict__ adj,
                 const __half* __restrict__ Bh,
                 const float* __restrict__ bias,
                 float* __restrict__ embed,
                 float* __restrict__ logp)
{
    extern __shared__ char sm[];
    const uint32_t sb = smem_u32(sm);
    const int tid  = threadIdx.x;
    const int lane = tid & 31, wid = tid >> 5;
    const int wm = wid >> 2, wn = wid & 3;
    const int mblk = blockIdx.x * BM2;

    float acc[2][8][4];
    #pragma unroll
    for (int i = 0; i < 2; i++)
        #pragma unroll
        for (int j = 0; j < 8; j++)
            #pragma unroll
            for (int q = 0; q < 4; q++) acc[i][j][q] = 0.0f;

    auto issueB = [&](int c, int s) {
        const size_t k0 = (size_t)c * BK2;
        #pragma unroll
        for (int i = 0; i < 8; i++) {
            int o = tid + i * 256;
            int row = o >> 3, kc = o & 7;
            uint32_t dst = sb + (uint32_t)s * SBST + (uint32_t)row * 128
                         + (uint32_t)((kc ^ (row & 7)) << 4);
            CP_ASYNC16(dst, Bh + (size_t)row * NROWS + k0 + kc * 8);
        }
    };
    const int arow_ = tid >> 2, aq = tid & 3;
    auto ldgA = [&](int c, float4 av[4]) {
        const float* p = adj + (size_t)(mblk + arow_) * NROWS + (size_t)c * BK2 + aq * 16;
        av[0] = reinterpret_cast<const float4*>(p)[0];
        av[1] = reinterpret_cast<const float4*>(p)[1];
        av[2] = reinterpret_cast<const float4*>(p)[2];
        av[3] = reinterpret_cast<const float4*>(p)[3];
    };
    auto storeA = [&](const float4 av[4], int d) {
        uint32_t w[8];
        #pragma unroll
        for (int i = 0; i < 4; i++) {
            __half2 h0 = __float22half2_rn(make_float2(av[i].x, av[i].y));
            __half2 h1 = __float22half2_rn(make_float2(av[i].z, av[i].w));
            w[2 * i]     = *reinterpret_cast<uint32_t*>(&h0);
            w[2 * i + 1] = *reinterpret_cast<uint32_t*>(&h1);
        }
        uint32_t base = sb + SA_OFF + (uint32_t)d * SAST + (uint32_t)arow_ * 128;
        uint32_t u0 = (uint32_t)((aq * 2) ^ (arow_ & 7)) << 4;
        uint32_t u1 = (uint32_t)((aq * 2 + 1) ^ (arow_ & 7)) << 4;
        asm volatile("st.shared.v4.b32 [%0], {%1,%2,%3,%4};" ::
            "r"(base + u0), "r"(w[0]), "r"(w[1]), "r"(w[2]), "r"(w[3]));
        asm volatile("st.shared.v4.b32 [%0], {%1,%2,%3,%4};" ::
            "r"(base + u1), "r"(w[4]), "r"(w[5]), "r"(w[6]), "r"(w[7]));
    };
    auto compute = [&](int bs, int ad) {
        const uint32_t baseB = sb + (uint32_t)bs * SBST;
        const uint32_t baseA = sb + SA_OFF + (uint32_t)ad * SAST;
        #pragma unroll
        for (int kk = 0; kk < 4; kk++) {
            uint32_t ah[2][4];
            const int arow = lane & 15;
            const int uA = kk * 2 + (lane >> 4);
            #pragma unroll
            for (int mi = 0; mi < 2; mi++) {
                int r = wm * 32 + mi * 16 + arow;
                LDSM4(ah[mi], baseA + (uint32_t)r * 128 + (uint32_t)((uA ^ (r & 7)) << 4));
            }
            #pragma unroll
            for (int g = 0; g < 4; g++) {
                const int nrow = wn * 64 + g * 16 + (lane & 7) + ((lane >> 4) << 3);
                const int uB = kk * 2 + ((lane >> 3) & 1);
                uint32_t bh[4];
                LDSM4(bh, baseB + (uint32_t)nrow * 128 + (uint32_t)((uB ^ (nrow & 7)) << 4));
                #pragma unroll
                for (int mi = 0; mi < 2; mi++)
                    #pragma unroll
                    for (int q = 0; q < 2; q++)
                        MMA16816(acc[mi][g * 2 + q], ah[mi], &bh[2 * q]);
            }
        }
    };

    issueB(0, 0); CP_COMMIT();
    issueB(1, 1); CP_COMMIT();
    float4 av[4];
    ldgA(0, av); storeA(av, 0);
    ldgA(1, av);

    // R7-proven order: wait -> barrier -> storeA -> compute -> issueB -> ldgA
    for (int c = 0; c < NCH2; ++c) {
        if (c < NCH2 - 1) CP_WAIT1(); else CP_WAIT0();
        __syncthreads();
        if (c + 1 < NCH2) storeA(av, (c + 1) & 1);
        compute(c % 3, c & 1);
        if (c + 2 < NCH2) { issueB(c + 2, (c + 2) % 3); CP_COMMIT(); }
        if (c + 2 < NCH2) ldgA(c + 2, av);
    }
    __syncthreads();

    #pragma unroll
    for (int ni = 0; ni < 8; ni++) {
        const float2 bv = __ldg(reinterpret_cast<const float2*>(
            bias + wn * 64 + ni * 8 + (lane & 3) * 2));
        #pragma unroll
        for (int mi = 0; mi < 2; mi++) {
            acc[mi][ni][0] += bv.x; acc[mi][ni][1] += bv.y;
            acc[mi][ni][2] += bv.x; acc[mi][ni][3] += bv.y;
        }
    }
    float* part  = reinterpret_cast<float*>(sm);
    float* part2 = reinterpret_cast<float*>(sm + 1024);
    float mx[2][2];
    #pragma unroll
    for (int mi = 0; mi < 2; mi++)
        #pragma unroll
        for (int rh = 0; rh < 2; rh++) {
            float m = -INFINITY;
            #pragma unroll
            for (int ni = 0; ni < 8; ni++)
                m = fmaxf(m, fmaxf(acc[mi][ni][rh * 2], acc[mi][ni][rh * 2 + 1]));
            m = fmaxf(m, __shfl_xor_sync(0xffffffffu, m, 1));
            m = fmaxf(m, __shfl_xor_sync(0xffffffffu, m, 2));
            mx[mi][rh] = m;
        }
    if ((lane & 3) == 0) {
        #pragma unroll
        for (int mi = 0; mi < 2; mi++)
            #pragma unroll
            for (int rh = 0; rh < 2; rh++)
                part[(wm * 32 + mi * 16 + (lane >> 2) + rh * 8) * 4 + wn] = mx[mi][rh];
    }
    __syncthreads();
    float rmax[2][2];
    #pragma unroll
    for (int mi = 0; mi < 2; mi++)
        #pragma unroll
        for (int rh = 0; rh < 2; rh++) {
            int r = wm * 32 + mi * 16 + (lane >> 2) + rh * 8;
            rmax[mi][rh] = fmaxf(fmaxf(part[r * 4], part[r * 4 + 1]),
                                 fmaxf(part[r * 4 + 2], part[r * 4 + 3]));
        }
    float sme[2][2];
    #pragma unroll
    for (int mi = 0; mi < 2; mi++)
        #pragma unroll
        for (int rh = 0; rh < 2; rh++) {
            float s = 0.0f;
            #pragma unroll
            for (int ni = 0; ni < 8; ni++)
                s += __expf(acc[mi][ni][rh * 2] - rmax[mi][rh])
                   + __expf(acc[mi][ni][rh * 2 + 1] - rmax[mi][rh]);
            s += __shfl_xor_sync(0xffffffffu, s, 1);
            s += __shfl_xor_sync(0xffffffffu, s, 2);
            sme[mi][rh] = s;
        }
    if ((lane & 3) == 0) {
        #pragma unroll
        for (int mi = 0; mi < 2; mi++)
            #pragma unroll
            for (int rh = 0; rh < 2; rh++)
                part2[(wm * 32 + mi * 16 + (lane >> 2) + rh * 8) * 4 + wn] = sme[mi][rh];
    }
    __syncthreads();
    float lse[2][2];
    #pragma unroll
    for (int mi = 0; mi < 2; mi++)
        #pragma unroll
        for (int rh = 0; rh < 2; rh++) {
            int r = wm * 32 + mi * 16 + (lane >> 2) + rh * 8;
            lse[mi][rh] = rmax[mi][rh] + __logf(part2[r * 4] + part2[r * 4 + 1]
                                              + part2[r * 4 + 2] + part2[r * 4 + 3]);
        }
    #pragma unroll
    for (int ni = 0; ni < 8; ni++) {
        const int col = wn * 64 + ni * 8 + (lane & 3) * 2;
        #pragma unroll
        for (int mi = 0; mi < 2; mi++) {
            const int r0 = mblk + wm * 32 + mi * 16 + (lane >> 2);
            const float* c = acc[mi][ni];
            *reinterpret_cast<float2*>(embed + (size_t)r0 * FHID + col) =
                make_float2(c[0], c[1]);
            *reinterpret_cast<float2*>(embed + (size_t)(r0 + 8) * FHID + col) =
                make_float2(c[2], c[3]);
            *reinterpret_cast<float2*>(logp + (size_t)r0 * FHID + col) =
                make_float2(c[0] - lse[mi][0], c[1] - lse[mi][0]);
            *reinterpret_cast<float2*>(logp + (size_t)(r0 + 8) * FHID + col) =
                make_float2(c[2] - lse[mi][1], c[3] - lse[mi][1]);
        }
    }
}

// ================= launch =================
extern "C" void kernel_launch(void* const* d_in, const int* in_sizes, int n_in,
                              void* d_out, int out_size)
{
    const float* x   = (const float*)d_in[0];
    const float* adj = (const float*)d_in[1];
    const float* W   = (const float*)d_in[2];
    const float* b   = (const float*)d_in[3];
    float* out = (float*)d_out;

    float* embed;
    __half *xh, *WTh, *sT;
    cudaGetSymbolAddress((void**)&xh,  g_xh);
    cudaGetSymbolAddress((void**)&WTh, g_WTh);
    cudaGetSymbolAddress((void**)&sT,  g_sT);

    float* logp = out;
    if (out_size >= 2 * NROWS * FHID) embed = out + (size_t)NROWS * FHID;
    else cudaGetSymbolAddress((void**)&embed, g_embed_fallback);

    cudaFuncSetAttribute(gemm1_hmma, cudaFuncAttributeMaxDynamicSharedMemorySize, G1_SMEM);
    cudaFuncSetAttribute(gemm2_fused, cudaFuncAttributeMaxDynamicSharedMemorySize, G2_SMEM);

    // prep: WT fp16, x fp16
    wt_half<<<dim3(FIN / 32, FHID / 32), 256>>>(W, WTh);
    x_half<<<(NROWS * FIN) / 1024, 256>>>(x, xh);
    // GEMM1 (HMMA, 1-term): sT = WT @ xT, fp16 out, already transposed
    gemm1_hmma<<<dim3(FHID / 64, NROWS / 256), 256, G1_SMEM>>>(WTh, xh, sT);
    // GEMM2 + bias + log_softmax fused
    gemm2_fused<<<NROWS / BM2, 256, G2_SMEM>>>(adj, sT, b, embed, logp);
}